// round 13
// baseline (speedup 1.0000x reference)
#include <cuda_runtime.h>
#include <stdint.h>

// ============================ problem constants ============================
#define BATCH 8192
#define DIMK  2048
#define UNITS 2048
#define KW    (DIMK / 32)        // 64 packed 32-bit words along K

#define BM 64                    // A-rows per CTA tile
#define BN 128                   // B-cols per CTA tile
#define NT 512                   // 16 warps; per-thread output tile 2x8
#define SROW 68                  // smem row stride in words (16B-aligned, LDS.128 conflict-free)
#define NTILES ((BATCH / BM) * (UNITS / BN))   // 2048

// Packed sign bits. Bit order (consistent between x and k, popc-invariant):
// group G = 128 consecutive K-elements -> words 4G..4G+3;
// word (4G + c) bit l = sign(element 128G + 4l + c).
__device__ uint32_t g_xbits[(size_t)BATCH * KW];   // [row][w]   2 MB
__device__ uint32_t g_kbits[(size_t)UNITS * KW];   // [unit][w]  0.5 MB
__device__ unsigned long long g_bar;               // monotonic ticket barrier

#define LOP3_(r, a, b, c, lut) \
    asm("lop3.b32 %0, %1, %2, %3, " #lut ";" : "=r"(r) : "r"(a), "r"(b), "r"(c))

__device__ __forceinline__ uint32_t smem_u32(const void* p) {
    uint32_t a;
    asm("{ .reg .u64 t; cvta.to.shared.u64 t, %1; cvt.u32.u64 %0, t; }" : "=r"(a) : "l"(p));
    return a;
}
__device__ __forceinline__ void cp8(uint32_t saddr, const void* gaddr) {
    asm volatile("cp.async.ca.shared.global [%0], [%1], 8;" :: "r"(saddr), "l"(gaddr));
}
__device__ __forceinline__ void cp_commit() {
    asm volatile("cp.async.commit_group;" ::: "memory");
}
template <int N>
__device__ __forceinline__ void cp_wait() {
    asm volatile("cp.async.wait_group %0;" :: "n"(N) : "memory");
}

// ---------------------------------------------------------------------------
// Persistent fused kernel: phase 1 packs both operands (grid-stride), a
// replay-safe ticket barrier (all CTAs resident at 2/SM), then phase 2 loops
// CTA tiles of the binary GEMM with the measured-best R10 mainloop.
// ---------------------------------------------------------------------------
extern __shared__ uint32_t smw[];   // sa[64*68] + sb[128*68] = 52224 B

__global__ void __launch_bounds__(NT, 2)
fused_kernel(const float* __restrict__ x, const float* __restrict__ k,
             const float* __restrict__ bias, float* __restrict__ out) {
    const int tid  = threadIdx.x;
    const int wid  = tid >> 5;
    const int lane = tid & 31;

    // ---------------- phase 1a: pack inputs (ballot path) ----------------
    // unit = 512 consecutive floats per warp -> 16 words.
    {
        const int nwarps = gridDim.x << 4;
        for (int u = (blockIdx.x << 4) + wid; u < (BATCH * DIMK) / 512; u += nwarps) {
            const float4* p = (const float4*)(x + (size_t)u * 512) + lane;
            uint32_t w[16];
#pragma unroll
            for (int it = 0; it < 4; ++it) {                    // group = 128 floats
                float4 v = p[it * 32];
                unsigned m0 = __ballot_sync(0xffffffffu, v.x >= 0.0f);
                unsigned m1 = __ballot_sync(0xffffffffu, v.y >= 0.0f);
                unsigned m2 = __ballot_sync(0xffffffffu, v.z >= 0.0f);
                unsigned m3 = __ballot_sync(0xffffffffu, v.w >= 0.0f);
                w[it * 4 + 0] = m0; w[it * 4 + 1] = m1;
                w[it * 4 + 2] = m2; w[it * 4 + 3] = m3;
            }
            if (lane < 16) g_xbits[(size_t)u * 16 + lane] = w[lane];
        }
    }
    // ---------------- phase 1b: pack kernel matrix (transpose) ----------------
    // task = w*2048 + n: consecutive threads -> consecutive n, coalesced.
    {
        const int nth = gridDim.x * NT;
        for (int task = blockIdx.x * NT + tid; task < KW * UNITS; task += nth) {
            const int w = task >> 11;
            const int n = task & 2047;
            const int G = w >> 2, c = w & 3;    // row(l) = 128G + 4l + c
            const float* col = k + ((size_t)(128 * G + c)) * UNITS + n;
            uint32_t bits = 0;
#pragma unroll
            for (int l = 0; l < 32; ++l) {
                bits |= (col[(size_t)(4 * l) * UNITS] >= 0.0f ? 1u : 0u) << l;
            }
            g_kbits[(size_t)n * KW + w] = bits;
        }
    }

    // ---------------- replay-safe grid barrier (all CTAs resident) ----------------
    __syncthreads();
    if (tid == 0) {
        __threadfence();
        unsigned long long t = atomicAdd(&g_bar, 1ULL);
        unsigned long long target = t - (t % (unsigned long long)gridDim.x)
                                    + (unsigned long long)gridDim.x;
        while (*(volatile unsigned long long*)&g_bar < target) { }
    }
    __syncthreads();
    __threadfence();

    // ---------------- phase 2: binary GEMM over persistent tiles ----------------
    uint32_t* sa = smw;                 // 64 rows
    uint32_t* sb = smw + BM * SROW;     // 128 rows
    const uint32_t sa_u = smem_u32(sa);
    const uint32_t sb_u = smem_u32(sb);

    const int tm = tid >> 4;   // 0..31, rows tm + 32*i (i<2)
    const int tn = tid & 15;   // 0..15, cols tn + 16*j (j<8)

    for (int t = blockIdx.x; t < NTILES; t += gridDim.x) {
        const int row0 = (t >> 4) * BM;
        const int col0 = (t & 15) * BN;

        // Async tile loads, one commit group per K-half (words [32h, 32h+32)).
#pragma unroll
        for (int h = 0; h < 2; ++h) {
#pragma unroll
            for (int it = 0; it < (BM * 16) / NT; ++it) {   // 2 iters for A
                const int idx = tid + it * NT;
                const int r = idx >> 4;
                const int p = idx & 15;
                const uint32_t woff = (uint32_t)(32 * h + 2 * p);
                cp8(sa_u + 4u * (r * SROW + woff),
                    (const char*)g_xbits + 4 * ((size_t)(row0 + r) * KW + woff));
            }
#pragma unroll
            for (int it = 0; it < (BN * 16) / NT; ++it) {   // 4 iters for B
                const int idx = tid + it * NT;
                const int r = idx >> 4;
                const int p = idx & 15;
                const uint32_t woff = (uint32_t)(32 * h + 2 * p);
                cp8(sb_u + 4u * (r * SROW + woff),
                    (const char*)g_kbits + 4 * ((size_t)(col0 + r) * KW + woff));
            }
            cp_commit();
        }

        int acc[2][8];
#pragma unroll
        for (int i = 0; i < 2; ++i)
#pragma unroll
            for (int j = 0; j < 8; ++j) acc[i][j] = 0;

        float bv[8];
#pragma unroll
        for (int j = 0; j < 8; ++j) bv[j] = bias[col0 + tn + 16 * j];

#pragma unroll
        for (int half = 0; half < 2; ++half) {
            if (half == 0) cp_wait<1>(); else cp_wait<0>();
            __syncthreads();

#pragma unroll 1
            for (int g = half * 4; g < half * 4 + 4; ++g) {
                const int wb = g * 8;

                uint32_t A[2][8];
#pragma unroll
                for (int i = 0; i < 2; ++i) {
                    const uint32_t* pa = sa + (tm + 32 * i) * SROW + wb;
                    uint4 v0 = *(const uint4*)(pa);
                    uint4 v1 = *(const uint4*)(pa + 4);
                    A[i][0] = v0.x; A[i][1] = v0.y; A[i][2] = v0.z; A[i][3] = v0.w;
                    A[i][4] = v1.x; A[i][5] = v1.y; A[i][6] = v1.z; A[i][7] = v1.w;
                }

#pragma unroll
                for (int j = 0; j < 8; ++j) {
                    const uint32_t* pb = sb + (tn + 16 * j) * SROW + wb;
                    uint4 u0 = *(const uint4*)(pb);
                    uint4 u1 = *(const uint4*)(pb + 4);
                    uint32_t B[8] = {u0.x, u0.y, u0.z, u0.w, u1.x, u1.y, u1.z, u1.w};
#pragma unroll
                    for (int i = 0; i < 2; ++i) {
                        uint32_t x0 = A[i][0] ^ B[0], x1 = A[i][1] ^ B[1];
                        uint32_t x2 = A[i][2] ^ B[2], x3 = A[i][3] ^ B[3];
                        uint32_t x4 = A[i][4] ^ B[4], x5 = A[i][5] ^ B[5];
                        uint32_t x6 = A[i][6] ^ B[6], x7 = A[i][7] ^ B[7];
                        uint32_t s1, c1, s2, c2, s3, c3, s4, c4;
                        LOP3_(s1, x0, x1, x2, 0x96);   // xor3
                        LOP3_(c1, x0, x1, x2, 0xE8);   // maj
                        LOP3_(s2, x3, x4, x5, 0x96);
                        LOP3_(c2, x3, x4, x5, 0xE8);
                        LOP3_(s3, s1, s2, x6, 0x96);
                        LOP3_(c3, s1, s2, x6, 0xE8);
                        LOP3_(s4, c1, c2, c3, 0x96);   // weight-2 plane
                        LOP3_(c4, c1, c2, c3, 0xE8);   // weight-4 plane
                        acc[i][j] += __popc(s3) + __popc(x7);
                        int tt = __popc(s4) + (__popc(c4) << 1);
                        acc[i][j] += tt << 1;
                    }
                }
            }
        }

        // Epilogue: out = DIM - 2*acc + bias.
#pragma unroll
        for (int i = 0; i < 2; ++i) {
            float* orow = out + (size_t)(row0 + tm + 32 * i) * UNITS + col0;
#pragma unroll
            for (int j = 0; j < 8; ++j) {
                orow[tn + 16 * j] = (float)(DIMK - 2 * acc[i][j]) + bv[j];
            }
        }

        // smem reuse hazard: next tile's cp.async must not overwrite data
        // other warps may still be reading.
        __syncthreads();
    }
}

// ============================ harness entry ============================
extern "C" void kernel_launch(void* const* d_in, const int* in_sizes, int n_in,
                              void* d_out, int out_size) {
    (void)in_sizes; (void)n_in; (void)out_size;
    const float* x    = (const float*)d_in[0];
    const float* k    = (const float*)d_in[1];
    const float* bias = (const float*)d_in[2];
    float* out        = (float*)d_out;

    const int SMEM_BYTES = (BM + BN) * SROW * 4;     // 52224
    cudaFuncSetAttribute(fused_kernel, cudaFuncAttributeMaxDynamicSharedMemorySize,
                         SMEM_BYTES);

    int sms = 148;
    cudaDeviceGetAttribute(&sms, cudaDevAttrMultiProcessorCount, 0);
    const int nCTA = 2 * sms;       // exactly-resident persistent grid

    fused_kernel<<<nCTA, NT, SMEM_BYTES>>>(x, k, bias, out);
}

// round 14
// speedup vs baseline: 1.1114x; 1.1114x over previous
#include <cuda_runtime.h>
#include <stdint.h>

// ============================ problem constants ============================
#define BATCH 8192
#define DIMK  2048
#define UNITS 2048
#define KW    (DIMK / 32)        // 64 packed 32-bit words along K

#define BM 64                    // A-rows per CTA
#define BN 128                   // B-cols per CTA
#define NT 512                   // 16 warps; per-thread output tile 2x8
#define SROW 68                  // smem row stride in words (16B-aligned, LDS.128 conflict-free)

// Packed sign bits. Bit order (consistent between x and k, popc-invariant):
// group G = 128 consecutive K-elements -> words 4G..4G+3;
// word (4G + c) bit l = sign(element 128G + 4l + c).
__device__ uint32_t g_xbits[(size_t)BATCH * KW];   // [row][w]   2 MB
__device__ uint32_t g_kbits[(size_t)UNITS * KW];   // [unit][w]  0.5 MB

#define LOP3_(r, a, b, c, lut) \
    asm("lop3.b32 %0, %1, %2, %3, " #lut ";" : "=r"(r) : "r"(a), "r"(b), "r"(c))

__device__ __forceinline__ uint32_t smem_u32(const void* p) {
    uint32_t a;
    asm("{ .reg .u64 t; cvta.to.shared.u64 t, %1; cvt.u32.u64 %0, t; }" : "=r"(a) : "l"(p));
    return a;
}
__device__ __forceinline__ void cp8(uint32_t saddr, const void* gaddr) {
    asm volatile("cp.async.ca.shared.global [%0], [%1], 8;" :: "r"(saddr), "l"(gaddr));
}
__device__ __forceinline__ void cp_commit() {
    asm volatile("cp.async.commit_group;" ::: "memory");
}
template <int N>
__device__ __forceinline__ void cp_wait() {
    asm volatile("cp.async.wait_group %0;" :: "n"(N) : "memory");
}

// ---------------------------------------------------------------------------
// Fused pack. Blocks [0, NXBLK): pack_x — each warp packs 1024 consecutive
// floats with 8 independent float4 loads in flight, then 8 ballot rounds,
// two 16-lane stores. Blocks [NXBLK, +512): pack_k transpose path.
// ---------------------------------------------------------------------------
#define NXBLK (BATCH * DIMK / (1024 * 8))   // 2048 blocks, 8 warps each
__global__ void pack_fused_kernel(const float* __restrict__ x, const float* __restrict__ k) {
    if (blockIdx.x < NXBLK) {
        const int warp = blockIdx.x * 8 + (threadIdx.x >> 5);   // 1024 floats per warp
        const int lane = threadIdx.x & 31;
        const float4* p = (const float4*)(x + (size_t)warp * 1024) + lane;
        float4 v[8];
#pragma unroll
        for (int it = 0; it < 8; ++it) v[it] = p[it * 32];      // 8 loads in flight
        uint32_t w[32];
#pragma unroll
        for (int it = 0; it < 8; ++it) {                        // group = 128 floats
            w[it * 4 + 0] = __ballot_sync(0xffffffffu, v[it].x >= 0.0f);
            w[it * 4 + 1] = __ballot_sync(0xffffffffu, v[it].y >= 0.0f);
            w[it * 4 + 2] = __ballot_sync(0xffffffffu, v[it].z >= 0.0f);
            w[it * 4 + 3] = __ballot_sync(0xffffffffu, v[it].w >= 0.0f);
        }
        uint32_t* dst = g_xbits + (size_t)warp * 32;
        if (lane < 16) dst[lane] = w[lane];
        else dst[lane] = w[lane];     // lanes 16..31 write w[16..31]
    } else {
        const int b = blockIdx.x - NXBLK;       // 0..511
        const int w = b & 63;                   // global word index
        const int n = (b >> 6) * 256 + threadIdx.x;
        const int G = w >> 2, c = w & 3;        // row(l) = 128G + 4l + c
        const float* col = k + ((size_t)(128 * G + c)) * UNITS + n;
        uint32_t bits = 0;
#pragma unroll
        for (int l = 0; l < 32; ++l) {
            bits |= (col[(size_t)(4 * l) * UNITS] >= 0.0f ? 1u : 0u) << l;
        }
        g_kbits[(size_t)n * KW + w] = bits;
    }
}

// ---------------------------------------------------------------------------
// Binary GEMM (measured-best R10 body): CSA popcount compression (8-word
// full-adder tree = alu/popc pipe balance point), LDS.128 reads, split-half
// cp.async pipelining, 2 CTAs/SM.
// out[r][c] = (DIMK + bias[c]) - 2*acc  via FFMA(-2, acc, bias+DIMK).
// ---------------------------------------------------------------------------
extern __shared__ uint32_t smw[];   // sa[64*68] + sb[128*68] = 52224 B

__global__ void __launch_bounds__(NT, 2)
bgemm_kernel(const float* __restrict__ bias, float* __restrict__ out) {
    uint32_t* sa = smw;                 // 64 rows
    uint32_t* sb = smw + BM * SROW;     // 128 rows

    const int tid  = threadIdx.x;
    const int row0 = blockIdx.y * BM;
    const int col0 = blockIdx.x * BN;

    const uint32_t sa_u = smem_u32(sa);
    const uint32_t sb_u = smem_u32(sb);

    // Async tile loads, one commit group per K-half (words [32h, 32h+32)).
#pragma unroll
    for (int h = 0; h < 2; ++h) {
#pragma unroll
        for (int it = 0; it < (BM * 16) / NT; ++it) {   // 2 iters for A
            const int idx = tid + it * NT;
            const int r = idx >> 4;
            const int p = idx & 15;
            const uint32_t woff = (uint32_t)(32 * h + 2 * p);
            cp8(sa_u + 4u * (r * SROW + woff),
                (const char*)g_xbits + 4 * ((size_t)(row0 + r) * KW + woff));
        }
#pragma unroll
        for (int it = 0; it < (BN * 16) / NT; ++it) {   // 4 iters for B
            const int idx = tid + it * NT;
            const int r = idx >> 4;
            const int p = idx & 15;
            const uint32_t woff = (uint32_t)(32 * h + 2 * p);
            cp8(sb_u + 4u * (r * SROW + woff),
                (const char*)g_kbits + 4 * ((size_t)(col0 + r) * KW + woff));
        }
        cp_commit();
    }

    const int tm = tid >> 4;   // 0..31, rows tm + 32*i (i<2)
    const int tn = tid & 15;   // 0..15, cols tn + 16*j (j<8)

    int acc[2][8];
#pragma unroll
    for (int i = 0; i < 2; ++i)
#pragma unroll
        for (int j = 0; j < 8; ++j) acc[i][j] = 0;

    // bias augmented with the +DIMK constant (exact in fp32)
    float bvd[8];
#pragma unroll
    for (int j = 0; j < 8; ++j) bvd[j] = __ldg(bias + col0 + tn + 16 * j) + (float)DIMK;

#pragma unroll
    for (int half = 0; half < 2; ++half) {
        if (half == 0) cp_wait<1>(); else cp_wait<0>();
        __syncthreads();

#pragma unroll 1
        for (int g = half * 4; g < half * 4 + 4; ++g) {
            const int wb = g * 8;

            uint32_t A[2][8];
#pragma unroll
            for (int i = 0; i < 2; ++i) {
                const uint32_t* pa = sa + (tm + 32 * i) * SROW + wb;
                uint4 v0 = *(const uint4*)(pa);
                uint4 v1 = *(const uint4*)(pa + 4);
                A[i][0] = v0.x; A[i][1] = v0.y; A[i][2] = v0.z; A[i][3] = v0.w;
                A[i][4] = v1.x; A[i][5] = v1.y; A[i][6] = v1.z; A[i][7] = v1.w;
            }

#pragma unroll
            for (int j = 0; j < 8; ++j) {
                const uint32_t* pb = sb + (tn + 16 * j) * SROW + wb;
                uint4 u0 = *(const uint4*)(pb);
                uint4 u1 = *(const uint4*)(pb + 4);
                uint32_t B[8] = {u0.x, u0.y, u0.z, u0.w, u1.x, u1.y, u1.z, u1.w};
#pragma unroll
                for (int i = 0; i < 2; ++i) {
                    uint32_t x0 = A[i][0] ^ B[0], x1 = A[i][1] ^ B[1];
                    uint32_t x2 = A[i][2] ^ B[2], x3 = A[i][3] ^ B[3];
                    uint32_t x4 = A[i][4] ^ B[4], x5 = A[i][5] ^ B[5];
                    uint32_t x6 = A[i][6] ^ B[6], x7 = A[i][7] ^ B[7];
                    uint32_t s1, c1, s2, c2, s3, c3, s4, c4;
                    LOP3_(s1, x0, x1, x2, 0x96);   // xor3
                    LOP3_(c1, x0, x1, x2, 0xE8);   // maj
                    LOP3_(s2, x3, x4, x5, 0x96);
                    LOP3_(c2, x3, x4, x5, 0xE8);
                    LOP3_(s3, s1, s2, x6, 0x96);
                    LOP3_(c3, s1, s2, x6, 0xE8);
                    LOP3_(s4, c1, c2, c3, 0x96);   // weight-2 plane
                    LOP3_(c4, c1, c2, c3, 0xE8);   // weight-4 plane
                    acc[i][j] += __popc(s3) + __popc(x7);
                    int t = __popc(s4) + (__popc(c4) << 1);
                    acc[i][j] += t << 1;
                }
            }
        }
    }

    // Epilogue: out = fma(-2, acc, bias + DIMK). Exact (small integers).
#pragma unroll
    for (int i = 0; i < 2; ++i) {
        float* orow = out + (size_t)(row0 + tm + 32 * i) * UNITS + col0;
#pragma unroll
        for (int j = 0; j < 8; ++j) {
            orow[tn + 16 * j] = fmaf(-2.0f, (float)acc[i][j], bvd[j]);
        }
    }
}

// ============================ harness entry ============================
extern "C" void kernel_launch(void* const* d_in, const int* in_sizes, int n_in,
                              void* d_out, int out_size) {
    (void)in_sizes; (void)n_in; (void)out_size;
    const float* x    = (const float*)d_in[0];
    const float* k    = (const float*)d_in[1];
    const float* bias = (const float*)d_in[2];
    float* out        = (float*)d_out;

    const int SMEM_BYTES = (BM + BN) * SROW * 4;     // 52224
    cudaFuncSetAttribute(bgemm_kernel, cudaFuncAttributeMaxDynamicSharedMemorySize,
                         SMEM_BYTES);

    pack_fused_kernel<<<NXBLK + KW * (UNITS / 256), 256>>>(x, k);
    bgemm_kernel<<<dim3(UNITS / BN, BATCH / BM), NT, SMEM_BYTES>>>(bias, out);
}